// round 1
// baseline (speedup 1.0000x reference)
#include <cuda_runtime.h>
#include <math.h>
#include <stdint.h>

#define NB 8192
#define ND 256

__device__ float d_sim[(size_t)NB * NB];
__device__ float d_row_term[NB];
__device__ float d_row_valid[NB];

// ---------------------------------------------------------------------------
// Kernel 1: sim = E * E^T  (fp32 SIMT GEMM), write full sim matrix.
// 128x128 tile per block, 256 threads, 8x8 per thread, BK=32.
// Smem layout: k-major [32][132] (pad to keep 16B alignment + spread banks).
// ---------------------------------------------------------------------------
__global__ void __launch_bounds__(256, 2) gemm_kernel(const float* __restrict__ emb) {
    __shared__ __align__(16) float sA[32 * 132];
    __shared__ __align__(16) float sB[32 * 132];

    const int r0 = blockIdx.y * 128;
    const int c0 = blockIdx.x * 128;
    const int tid = threadIdx.x;
    const int ty = tid >> 4;    // 0..15
    const int tx = tid & 15;    // 0..15
    const int lrow = tid >> 3;  // 0..31
    const int c4 = tid & 7;     // 0..7  (float4 column within 32-wide k slice)

    float acc[8][8];
#pragma unroll
    for (int i = 0; i < 8; i++)
#pragma unroll
        for (int j = 0; j < 8; j++) acc[i][j] = 0.0f;

    for (int k0 = 0; k0 < ND; k0 += 32) {
#pragma unroll
        for (int l = 0; l < 4; l++) {
            int row = lrow + 32 * l;
            float4 va = *(const float4*)&emb[(size_t)(r0 + row) * ND + k0 + c4 * 4];
            float4 vb = *(const float4*)&emb[(size_t)(c0 + row) * ND + k0 + c4 * 4];
            int kk = c4 * 4;
            sA[(kk + 0) * 132 + row] = va.x;
            sA[(kk + 1) * 132 + row] = va.y;
            sA[(kk + 2) * 132 + row] = va.z;
            sA[(kk + 3) * 132 + row] = va.w;
            sB[(kk + 0) * 132 + row] = vb.x;
            sB[(kk + 1) * 132 + row] = vb.y;
            sB[(kk + 2) * 132 + row] = vb.z;
            sB[(kk + 3) * 132 + row] = vb.w;
        }
        __syncthreads();

#pragma unroll 4
        for (int k = 0; k < 32; k++) {
            float4 a0 = *(const float4*)&sA[k * 132 + ty * 8];
            float4 a1 = *(const float4*)&sA[k * 132 + ty * 8 + 4];
            float4 b0 = *(const float4*)&sB[k * 132 + tx * 8];
            float4 b1 = *(const float4*)&sB[k * 132 + tx * 8 + 4];
            float a[8] = {a0.x, a0.y, a0.z, a0.w, a1.x, a1.y, a1.z, a1.w};
            float b[8] = {b0.x, b0.y, b0.z, b0.w, b1.x, b1.y, b1.z, b1.w};
#pragma unroll
            for (int i = 0; i < 8; i++)
#pragma unroll
                for (int j = 0; j < 8; j++) acc[i][j] = fmaf(a[i], b[j], acc[i][j]);
        }
        __syncthreads();
    }

#pragma unroll
    for (int i = 0; i < 8; i++) {
        size_t base = (size_t)(r0 + ty * 8 + i) * NB + c0 + tx * 8;
        *(float4*)&d_sim[base]     = make_float4(acc[i][0], acc[i][1], acc[i][2], acc[i][3]);
        *(float4*)&d_sim[base + 4] = make_float4(acc[i][4], acc[i][5], acc[i][6], acc[i][7]);
    }
}

// ---------------------------------------------------------------------------
// Kernel 2: per-row pos_min/neg_max, then masked exp-sums -> per-row term.
// One block (256 threads) per row. Second pass re-reads the row from L1.
// ---------------------------------------------------------------------------
__global__ void __launch_bounds__(256) row_kernel(const int* __restrict__ labels) {
    const int i = blockIdx.x;
    const int tid = threadIdx.x;
    const int li = labels[i];
    const float* __restrict__ row = &d_sim[(size_t)i * NB];

    const float ALPHA = 2.0f, BETA = 50.0f, BASE = 0.5f, MARGIN = 0.1f;

    float pmin = INFINITY, nmax = -INFINITY;
    for (int j = tid; j < NB; j += 256) {
        float s = row[j];
        int lj = labels[j];
        if (lj == li) {
            if (j != i) pmin = fminf(pmin, s);
        } else {
            nmax = fmaxf(nmax, s);
        }
    }

    __shared__ float red[256];
    red[tid] = pmin;
    __syncthreads();
    for (int o = 128; o > 0; o >>= 1) {
        if (tid < o) red[tid] = fminf(red[tid], red[tid + o]);
        __syncthreads();
    }
    pmin = red[0];
    __syncthreads();
    red[tid] = nmax;
    __syncthreads();
    for (int o = 128; o > 0; o >>= 1) {
        if (tid < o) red[tid] = fmaxf(red[tid], red[tid + o]);
        __syncthreads();
    }
    nmax = red[0];
    __syncthreads();

    // Nonemptiness of hard masks, matching reference inequality forms exactly.
    bool anyP = (pmin - MARGIN < nmax);   // exists hard positive
    bool anyN = (nmax + MARGIN > pmin);   // exists hard negative
    if (!(anyP && anyN)) {
        if (tid == 0) { d_row_term[i] = 0.0f; d_row_valid[i] = 0.0f; }
        return;
    }

    // LSE shifts: max over hard mask of score, clamped with the implicit 0.
    // min over hard_pos == pmin; max over hard_neg == nmax (monotonicity).
    float m_pos = fmaxf(-ALPHA * (pmin - BASE), 0.0f);
    float m_neg = fmaxf(BETA * (nmax - BASE), 0.0f);

    float sp = 0.0f, sn = 0.0f;
    for (int j = tid; j < NB; j += 256) {
        float s = row[j];
        int lj = labels[j];
        if (lj == li) {
            if (j != i && (s - MARGIN < nmax))
                sp += expf(-ALPHA * (s - BASE) - m_pos);
        } else {
            if (s + MARGIN > pmin)
                sn += expf(BETA * (s - BASE) - m_neg);
        }
    }

    red[tid] = sp;
    __syncthreads();
    for (int o = 128; o > 0; o >>= 1) {
        if (tid < o) red[tid] += red[tid + o];
        __syncthreads();
    }
    sp = red[0];
    __syncthreads();
    red[tid] = sn;
    __syncthreads();
    for (int o = 128; o > 0; o >>= 1) {
        if (tid < o) red[tid] += red[tid + o];
        __syncthreads();
    }
    sn = red[0];

    if (tid == 0) {
        float pt = (logf(expf(-m_pos) + sp) + m_pos) / ALPHA;
        float nt = (logf(expf(-m_neg) + sn) + m_neg) / BETA;
        d_row_term[i] = pt + nt;
        d_row_valid[i] = 1.0f;
    }
}

// ---------------------------------------------------------------------------
// Kernel 3: deterministic final reduction.
// ---------------------------------------------------------------------------
__global__ void __launch_bounds__(256) final_kernel(float* __restrict__ out) {
    const int tid = threadIdx.x;
    float t = 0.0f, v = 0.0f;
    for (int j = tid; j < NB; j += 256) {
        t += d_row_term[j];
        v += d_row_valid[j];
    }
    __shared__ float rt[256], rv[256];
    rt[tid] = t;
    rv[tid] = v;
    __syncthreads();
    for (int o = 128; o > 0; o >>= 1) {
        if (tid < o) { rt[tid] += rt[tid + o]; rv[tid] += rv[tid + o]; }
        __syncthreads();
    }
    if (tid == 0) out[0] = rt[0] / fmaxf(rv[0], 1.0f);
}

extern "C" void kernel_launch(void* const* d_in, const int* in_sizes, int n_in,
                              void* d_out, int out_size) {
    const float* emb = (const float*)d_in[0];
    const int* labels = (const int*)d_in[1];
    float* out = (float*)d_out;

    dim3 gg(NB / 128, NB / 128);
    gemm_kernel<<<gg, 256>>>(emb);
    row_kernel<<<NB, 256>>>(labels);
    final_kernel<<<1, 256>>>(out);
}

// round 4
// speedup vs baseline: 3.1025x; 3.1025x over previous
#include <cuda_runtime.h>
#include <math.h>
#include <stdint.h>

#define NB 8192
#define ND 256

__device__ float d_sim[(size_t)NB * NB];
__device__ float d_embr[(size_t)NB * ND];
__device__ float d_row_term[NB];
__device__ float d_row_valid[NB];

// ---------------- helpers ----------------
__device__ __forceinline__ uint32_t smem_u32(const void* p) {
    uint32_t a;
    asm("{ .reg .u64 t; cvta.to.shared.u64 t, %1; cvt.u32.u64 %0, t; }" : "=r"(a) : "l"(p));
    return a;
}
__device__ __forceinline__ void cp16(uint32_t dst, const void* src) {
    asm volatile("cp.async.cg.shared.global [%0], [%1], 16;" :: "r"(dst), "l"(src) : "memory");
}
__device__ __forceinline__ void cp_commit() {
    asm volatile("cp.async.commit_group;" ::: "memory");
}
template <int N>
__device__ __forceinline__ void cp_wait() {
    asm volatile("cp.async.wait_group %0;" :: "n"(N) : "memory");
}
__device__ __forceinline__ void cp_wait_n(int n) {
    if (n == 0) cp_wait<0>();
    else if (n == 1) cp_wait<1>();
    else cp_wait<2>();
}
__device__ __forceinline__ void ldsm4(uint32_t r[4], uint32_t addr) {
    asm volatile("ldmatrix.sync.aligned.m8n8.x4.shared.b16 {%0,%1,%2,%3}, [%4];"
                 : "=r"(r[0]), "=r"(r[1]), "=r"(r[2]), "=r"(r[3]) : "r"(addr));
}
__device__ __forceinline__ void mma8(float c[4], const uint32_t a[4], uint32_t b0, uint32_t b1) {
    asm volatile(
        "mma.sync.aligned.m16n8k8.row.col.f32.tf32.tf32.f32 "
        "{%0,%1,%2,%3}, {%4,%5,%6,%7}, {%8,%9}, {%0,%1,%2,%3};"
        : "+f"(c[0]), "+f"(c[1]), "+f"(c[2]), "+f"(c[3])
        : "r"(a[0]), "r"(a[1]), "r"(a[2]), "r"(a[3]), "r"(b0), "r"(b1));
}

// ---------------------------------------------------------------------------
// Kernel 0: round embeddings to tf32 (rna) once.
// ---------------------------------------------------------------------------
__global__ void __launch_bounds__(256) round_kernel(const float* __restrict__ emb) {
    int i = blockIdx.x * 256 + threadIdx.x;  // float4 index
    float4 v = ((const float4*)emb)[i];
    uint32_t x, y, z, w;
    asm("cvt.rna.tf32.f32 %0, %1;" : "=r"(x) : "f"(v.x));
    asm("cvt.rna.tf32.f32 %0, %1;" : "=r"(y) : "f"(v.y));
    asm("cvt.rna.tf32.f32 %0, %1;" : "=r"(z) : "f"(v.z));
    asm("cvt.rna.tf32.f32 %0, %1;" : "=r"(w) : "f"(v.w));
    ((uint4*)d_embr)[i] = make_uint4(x, y, z, w);
}

// ---------------------------------------------------------------------------
// Kernel 1: sim = E*E^T via tf32 mma.sync, upper-triangle tiles only.
// CTA 128x128, 8 warps (2m x 4n), warp tile 64x32, BK=32, 3-stage cp.async.
// ---------------------------------------------------------------------------
#define STG_BYTES 32768
#define SMEM_GEMM 98304

__global__ void __launch_bounds__(256, 2) gemm_kernel() {
    const int bi = blockIdx.y, bj = blockIdx.x;
    if (bj < bi) return;

    extern __shared__ __align__(16) char smem[];
    uint32_t sb = smem_u32(smem);
    const int tid = threadIdx.x, lane = tid & 31, wid = tid >> 5;
    const int mwarp = (wid >> 2) * 64, nwarp = (wid & 3) * 32;
    const int r0 = bi * 128, c0 = bj * 128;
    const float* __restrict__ embA = d_embr + (size_t)r0 * ND;
    const float* __restrict__ embB = d_embr + (size_t)c0 * ND;

    float acc[4][4][4] = {};

    // ldmatrix per-lane address components (swizzle: chunk ^= row&7)
    const int aRow = lane & 15;
    const int aCk = lane >> 4;
    const int bRow = (lane & 7) | ((lane & 16) >> 1);
    const int bCk = (lane >> 3) & 1;
    const int sw = lane & 7;

    auto load_stage = [&](int s) {
        uint32_t base = sb + (s % 3) * STG_BYTES;
        int k0 = s * 32;
#pragma unroll
        for (int it = 0; it < 4; it++) {  // A: 1024 16B chunks
            int task = it * 256 + tid;
            int r = task >> 3, c = task & 7;
            cp16(base + r * 128 + ((c ^ (r & 7)) << 4),
                 embA + (size_t)r * ND + k0 + c * 4);
        }
#pragma unroll
        for (int it = 0; it < 4; it++) {  // B: 1024 16B chunks
            int task = it * 256 + tid;
            int r = task >> 3, c = task & 7;
            cp16(base + 16384 + r * 128 + ((c ^ (r & 7)) << 4),
                 embB + (size_t)r * ND + k0 + c * 4);
        }
        cp_commit();
    };

    load_stage(0);
    load_stage(1);
    load_stage(2);

    for (int s = 0; s < 8; s++) {
        int pend = 7 - s;
        cp_wait_n(pend < 2 ? pend : 2);
        __syncthreads();
        uint32_t sA = sb + (s % 3) * STG_BYTES + mwarp * 128;
        uint32_t sB = sb + (s % 3) * STG_BYTES + 16384 + nwarp * 128;
#pragma unroll
        for (int ks = 0; ks < 4; ks++) {
            uint32_t a[4][4], b[2][4];
#pragma unroll
            for (int mf = 0; mf < 4; mf++)
                ldsm4(a[mf], sA + mf * 2048 + aRow * 128 + (((ks * 2 + aCk) ^ sw) << 4));
#pragma unroll
            for (int nf2 = 0; nf2 < 2; nf2++)
                ldsm4(b[nf2], sB + nf2 * 2048 + bRow * 128 + (((ks * 2 + bCk) ^ sw) << 4));
#pragma unroll
            for (int mf = 0; mf < 4; mf++)
#pragma unroll
                for (int nf = 0; nf < 4; nf++)
                    mma8(acc[mf][nf], a[mf], b[nf >> 1][(nf & 1) * 2], b[nf >> 1][(nf & 1) * 2 + 1]);
        }
        __syncthreads();
        if (s + 3 < 8) load_stage(s + 3);
    }

    // Epilogue: stage C into smem (stride 129 -> conflict-free row AND col reads)
    float* Cbuf = (float*)smem;
#pragma unroll
    for (int mf = 0; mf < 4; mf++) {
        int rb = mwarp + mf * 16 + (lane >> 2);
#pragma unroll
        for (int nf = 0; nf < 4; nf++) {
            int cb = nwarp + nf * 8 + 2 * (lane & 3);
            Cbuf[rb * 129 + cb] = acc[mf][nf][0];
            Cbuf[rb * 129 + cb + 1] = acc[mf][nf][1];
            Cbuf[(rb + 8) * 129 + cb] = acc[mf][nf][2];
            Cbuf[(rb + 8) * 129 + cb + 1] = acc[mf][nf][3];
        }
    }
    __syncthreads();

    // direct tile (bi,bj)
    for (int idx = tid; idx < 16384; idx += 256) {
        int r = idx >> 7, c = idx & 127;
        d_sim[(size_t)(r0 + r) * NB + c0 + c] = Cbuf[r * 129 + c];
    }
    // transposed tile (bj,bi)
    if (bi != bj) {
        for (int idx = tid; idx < 16384; idx += 256) {
            int rt = idx >> 7, ct = idx & 127;
            d_sim[(size_t)(c0 + rt) * NB + r0 + ct] = Cbuf[ct * 129 + rt];
        }
    }
}

// ---------------------------------------------------------------------------
// Kernel 2: per-row min/max + masked exp sums (smem-cached row).
// ---------------------------------------------------------------------------
__global__ void __launch_bounds__(256) row_kernel(const int* __restrict__ labels) {
    extern __shared__ char rsm[];
    float* srow = (float*)rsm;
    int* slab = (int*)(rsm + 32768);
    __shared__ float red[256];

    const int i = blockIdx.x;
    const int tid = threadIdx.x;
    const int li = labels[i];
    const float* __restrict__ row = &d_sim[(size_t)i * NB];

    const float ALPHA = 2.0f, BETA = 50.0f, BASE = 0.5f, MARGIN = 0.1f;

    float pmin = INFINITY, nmax = -INFINITY;
    for (int j4 = tid; j4 < NB / 4; j4 += 256) {
        float4 s4 = ((const float4*)row)[j4];
        int4 l4 = ((const int4*)labels)[j4];
        ((float4*)srow)[j4] = s4;
        ((int4*)slab)[j4] = l4;
        int j = j4 * 4;
        float sv[4] = {s4.x, s4.y, s4.z, s4.w};
        int lv[4] = {l4.x, l4.y, l4.z, l4.w};
#pragma unroll
        for (int e = 0; e < 4; e++) {
            if (lv[e] == li) {
                if (j + e != i) pmin = fminf(pmin, sv[e]);
            } else {
                nmax = fmaxf(nmax, sv[e]);
            }
        }
    }

    red[tid] = pmin; __syncthreads();
    for (int o = 128; o > 0; o >>= 1) {
        if (tid < o) red[tid] = fminf(red[tid], red[tid + o]);
        __syncthreads();
    }
    pmin = red[0]; __syncthreads();
    red[tid] = nmax; __syncthreads();
    for (int o = 128; o > 0; o >>= 1) {
        if (tid < o) red[tid] = fmaxf(red[tid], red[tid + o]);
        __syncthreads();
    }
    nmax = red[0]; __syncthreads();

    bool anyP = (pmin - MARGIN < nmax);
    bool anyN = (nmax + MARGIN > pmin);
    if (!(anyP && anyN)) {
        if (tid == 0) { d_row_term[i] = 0.0f; d_row_valid[i] = 0.0f; }
        return;
    }

    float m_pos = fmaxf(-ALPHA * (pmin - BASE), 0.0f);
    float m_neg = fmaxf(BETA * (nmax - BASE), 0.0f);

    float sp = 0.0f, sn = 0.0f;
    for (int j4 = tid; j4 < NB / 4; j4 += 256) {
        float4 s4 = ((const float4*)srow)[j4];
        int4 l4 = ((const int4*)slab)[j4];
        int j = j4 * 4;
        float sv[4] = {s4.x, s4.y, s4.z, s4.w};
        int lv[4] = {l4.x, l4.y, l4.z, l4.w};
#pragma unroll
        for (int e = 0; e < 4; e++) {
            float s = sv[e];
            if (lv[e] == li) {
                if (j + e != i && (s - MARGIN < nmax))
                    sp += expf(-ALPHA * (s - BASE) - m_pos);
            } else {
                if (s + MARGIN > pmin)
                    sn += expf(BETA * (s - BASE) - m_neg);
            }
        }
    }

    red[tid] = sp; __syncthreads();
    for (int o = 128; o > 0; o >>= 1) {
        if (tid < o) red[tid] += red[tid + o];
        __syncthreads();
    }
    sp = red[0]; __syncthreads();
    red[tid] = sn; __syncthreads();
    for (int o = 128; o > 0; o >>= 1) {
        if (tid < o) red[tid] += red[tid + o];
        __syncthreads();
    }
    sn = red[0];

    if (tid == 0) {
        float pt = (logf(expf(-m_pos) + sp) + m_pos) / ALPHA;
        float nt = (logf(expf(-m_neg) + sn) + m_neg) / BETA;
        d_row_term[i] = pt + nt;
        d_row_valid[i] = 1.0f;
    }
}

__global__ void __launch_bounds__(256) final_kernel(float* __restrict__ out) {
    const int tid = threadIdx.x;
    float t = 0.0f, v = 0.0f;
    for (int j = tid; j < NB; j += 256) {
        t += d_row_term[j];
        v += d_row_valid[j];
    }
    __shared__ float rt[256], rv[256];
    rt[tid] = t; rv[tid] = v;
    __syncthreads();
    for (int o = 128; o > 0; o >>= 1) {
        if (tid < o) { rt[tid] += rt[tid + o]; rv[tid] += rv[tid + o]; }
        __syncthreads();
    }
    if (tid == 0) out[0] = rt[0] / fmaxf(rv[0], 1.0f);
}

extern "C" void kernel_launch(void* const* d_in, const int* in_sizes, int n_in,
                              void* d_out, int out_size) {
    const float* emb = (const float*)d_in[0];
    const int* labels = (const int*)d_in[1];
    float* out = (float*)d_out;

    cudaFuncSetAttribute(gemm_kernel, cudaFuncAttributeMaxDynamicSharedMemorySize, SMEM_GEMM);
    cudaFuncSetAttribute(row_kernel, cudaFuncAttributeMaxDynamicSharedMemorySize, 65536);

    round_kernel<<<(NB * ND / 4) / 256, 256>>>(emb);
    gemm_kernel<<<dim3(64, 64), 256, SMEM_GEMM>>>();
    row_kernel<<<NB, 256, 65536>>>(labels);
    final_kernel<<<1, 256>>>(out);
}

// round 5
// speedup vs baseline: 3.8504x; 1.2410x over previous
#include <cuda_runtime.h>
#include <cuda_bf16.h>
#include <math.h>
#include <stdint.h>

#define NB 8192
#define ND 256

__device__ __nv_bfloat16 d_sim[(size_t)NB * NB];   // 128 MB
__device__ float d_embr[(size_t)NB * ND];
__device__ float d_row_term[NB];
__device__ float d_row_valid[NB];

// ---------------- helpers ----------------
__device__ __forceinline__ uint32_t smem_u32(const void* p) {
    uint32_t a;
    asm("{ .reg .u64 t; cvta.to.shared.u64 t, %1; cvt.u32.u64 %0, t; }" : "=r"(a) : "l"(p));
    return a;
}
__device__ __forceinline__ void cp16(uint32_t dst, const void* src) {
    asm volatile("cp.async.cg.shared.global [%0], [%1], 16;" :: "r"(dst), "l"(src) : "memory");
}
__device__ __forceinline__ void cp_commit() {
    asm volatile("cp.async.commit_group;" ::: "memory");
}
template <int N>
__device__ __forceinline__ void cp_wait() {
    asm volatile("cp.async.wait_group %0;" :: "n"(N) : "memory");
}
__device__ __forceinline__ void cp_wait_n(int n) {
    if (n == 0) cp_wait<0>();
    else if (n == 1) cp_wait<1>();
    else cp_wait<2>();
}
__device__ __forceinline__ void ldsm4(uint32_t r[4], uint32_t addr) {
    asm volatile("ldmatrix.sync.aligned.m8n8.x4.shared.b16 {%0,%1,%2,%3}, [%4];"
                 : "=r"(r[0]), "=r"(r[1]), "=r"(r[2]), "=r"(r[3]) : "r"(addr));
}
__device__ __forceinline__ void mma8(float c[4], const uint32_t a[4], uint32_t b0, uint32_t b1) {
    asm volatile(
        "mma.sync.aligned.m16n8k8.row.col.f32.tf32.tf32.f32 "
        "{%0,%1,%2,%3}, {%4,%5,%6,%7}, {%8,%9}, {%0,%1,%2,%3};"
        : "+f"(c[0]), "+f"(c[1]), "+f"(c[2]), "+f"(c[3])
        : "r"(a[0]), "r"(a[1]), "r"(a[2]), "r"(a[3]), "r"(b0), "r"(b1));
}

// ---------------------------------------------------------------------------
// Kernel 0: round embeddings to tf32 (rna) once.
// ---------------------------------------------------------------------------
__global__ void __launch_bounds__(256) round_kernel(const float* __restrict__ emb) {
    int i = blockIdx.x * 256 + threadIdx.x;
    float4 v = ((const float4*)emb)[i];
    uint32_t x, y, z, w;
    asm("cvt.rna.tf32.f32 %0, %1;" : "=r"(x) : "f"(v.x));
    asm("cvt.rna.tf32.f32 %0, %1;" : "=r"(y) : "f"(v.y));
    asm("cvt.rna.tf32.f32 %0, %1;" : "=r"(z) : "f"(v.z));
    asm("cvt.rna.tf32.f32 %0, %1;" : "=r"(w) : "f"(v.w));
    ((uint4*)d_embr)[i] = make_uint4(x, y, z, w);
}

// ---------------------------------------------------------------------------
// Kernel 1: sim = E*E^T via tf32 mma.sync, upper-triangle tiles only.
// CTA 128x128, 8 warps (2m x 4n), warp tile 64x32, BK=32, 3-stage cp.async.
// Epilogue converts to bf16 and writes the tile + its transpose.
// ---------------------------------------------------------------------------
#define STG_BYTES 32768
#define SMEM_GEMM 98304

__global__ void __launch_bounds__(256, 2) gemm_kernel() {
    const int bi = blockIdx.y, bj = blockIdx.x;
    if (bj < bi) return;

    extern __shared__ __align__(16) char smem[];
    uint32_t sb = smem_u32(smem);
    const int tid = threadIdx.x, lane = tid & 31, wid = tid >> 5;
    const int mwarp = (wid >> 2) * 64, nwarp = (wid & 3) * 32;
    const int r0 = bi * 128, c0 = bj * 128;
    const float* __restrict__ embA = d_embr + (size_t)r0 * ND;
    const float* __restrict__ embB = d_embr + (size_t)c0 * ND;

    float acc[4][4][4] = {};

    const int aRow = lane & 15;
    const int aCk = lane >> 4;
    const int bRow = (lane & 7) | ((lane & 16) >> 1);
    const int bCk = (lane >> 3) & 1;
    const int sw = lane & 7;

    auto load_stage = [&](int s) {
        uint32_t base = sb + (s % 3) * STG_BYTES;
        int k0 = s * 32;
#pragma unroll
        for (int it = 0; it < 4; it++) {
            int task = it * 256 + tid;
            int r = task >> 3, c = task & 7;
            cp16(base + r * 128 + ((c ^ (r & 7)) << 4),
                 embA + (size_t)r * ND + k0 + c * 4);
        }
#pragma unroll
        for (int it = 0; it < 4; it++) {
            int task = it * 256 + tid;
            int r = task >> 3, c = task & 7;
            cp16(base + 16384 + r * 128 + ((c ^ (r & 7)) << 4),
                 embB + (size_t)r * ND + k0 + c * 4);
        }
        cp_commit();
    };

    load_stage(0);
    load_stage(1);
    load_stage(2);

    for (int s = 0; s < 8; s++) {
        int pend = 7 - s;
        cp_wait_n(pend < 2 ? pend : 2);
        __syncthreads();
        uint32_t sA = sb + (s % 3) * STG_BYTES + mwarp * 128;
        uint32_t sB = sb + (s % 3) * STG_BYTES + 16384 + nwarp * 128;
#pragma unroll
        for (int ks = 0; ks < 4; ks++) {
            uint32_t a[4][4], b[2][4];
#pragma unroll
            for (int mf = 0; mf < 4; mf++)
                ldsm4(a[mf], sA + mf * 2048 + aRow * 128 + (((ks * 2 + aCk) ^ sw) << 4));
#pragma unroll
            for (int nf2 = 0; nf2 < 2; nf2++)
                ldsm4(b[nf2], sB + nf2 * 2048 + bRow * 128 + (((ks * 2 + bCk) ^ sw) << 4));
#pragma unroll
            for (int mf = 0; mf < 4; mf++)
#pragma unroll
                for (int nf = 0; nf < 4; nf++)
                    mma8(acc[mf][nf], a[mf], b[nf >> 1][(nf & 1) * 2], b[nf >> 1][(nf & 1) * 2 + 1]);
        }
        __syncthreads();
        if (s + 3 < 8) load_stage(s + 3);
    }

    // Epilogue: stage fp32 C into smem (stride 129), emit bf16 direct + transposed.
    float* Cbuf = (float*)smem;
#pragma unroll
    for (int mf = 0; mf < 4; mf++) {
        int rb = mwarp + mf * 16 + (lane >> 2);
#pragma unroll
        for (int nf = 0; nf < 4; nf++) {
            int cb = nwarp + nf * 8 + 2 * (lane & 3);
            Cbuf[rb * 129 + cb] = acc[mf][nf][0];
            Cbuf[rb * 129 + cb + 1] = acc[mf][nf][1];
            Cbuf[(rb + 8) * 129 + cb] = acc[mf][nf][2];
            Cbuf[(rb + 8) * 129 + cb + 1] = acc[mf][nf][3];
        }
    }
    __syncthreads();

    // direct tile (bi,bj): bf16x2 stores, coalesced
    for (int idx = tid; idx < 8192; idx += 256) {
        int r = idx >> 6, c2 = (idx & 63) * 2;
        float2 v = make_float2(Cbuf[r * 129 + c2], Cbuf[r * 129 + c2 + 1]);
        *(__nv_bfloat162*)&d_sim[(size_t)(r0 + r) * NB + c0 + c2] = __float22bfloat162_rn(v);
    }
    // transposed tile (bj,bi)
    if (bi != bj) {
        for (int idx = tid; idx < 8192; idx += 256) {
            int rt = idx >> 6, ct2 = (idx & 63) * 2;
            float2 v = make_float2(Cbuf[ct2 * 129 + rt], Cbuf[(ct2 + 1) * 129 + rt]);
            *(__nv_bfloat162*)&d_sim[(size_t)(c0 + rt) * NB + r0 + ct2] = __float22bfloat162_rn(v);
        }
    }
}

// ---------------------------------------------------------------------------
// Kernel 2: per-row min/max + masked exp sums (bf16 row + labels in smem).
// ---------------------------------------------------------------------------
__global__ void __launch_bounds__(256) row_kernel(const int* __restrict__ labels) {
    extern __shared__ char rsm[];
    __nv_bfloat16* srow = (__nv_bfloat16*)rsm;   // 16 KB
    int* slab = (int*)(rsm + 16384);             // 32 KB
    __shared__ float red[256];

    const int i = blockIdx.x;
    const int tid = threadIdx.x;
    const int li = labels[i];
    const __nv_bfloat16* __restrict__ row = &d_sim[(size_t)i * NB];

    const float ALPHA = 2.0f, BETA = 50.0f, BASE = 0.5f, MARGIN = 0.1f;

    float pmin = INFINITY, nmax = -INFINITY;
    for (int j8 = tid; j8 < NB / 8; j8 += 256) {
        uint4 sraw = ((const uint4*)row)[j8];
        ((uint4*)srow)[j8] = sraw;
        int4 la = ((const int4*)labels)[j8 * 2];
        int4 lb = ((const int4*)labels)[j8 * 2 + 1];
        ((int4*)slab)[j8 * 2] = la;
        ((int4*)slab)[j8 * 2 + 1] = lb;

        float f[8];
        const __nv_bfloat162* p = (const __nv_bfloat162*)&sraw;
#pragma unroll
        for (int e = 0; e < 4; e++) {
            float2 v = __bfloat1622float2(p[e]);
            f[2 * e] = v.x;
            f[2 * e + 1] = v.y;
        }
        int lv[8] = {la.x, la.y, la.z, la.w, lb.x, lb.y, lb.z, lb.w};
        int j = j8 * 8;
#pragma unroll
        for (int e = 0; e < 8; e++) {
            if (lv[e] == li) {
                if (j + e != i) pmin = fminf(pmin, f[e]);
            } else {
                nmax = fmaxf(nmax, f[e]);
            }
        }
    }

    red[tid] = pmin; __syncthreads();
    for (int o = 128; o > 0; o >>= 1) {
        if (tid < o) red[tid] = fminf(red[tid], red[tid + o]);
        __syncthreads();
    }
    pmin = red[0]; __syncthreads();
    red[tid] = nmax; __syncthreads();
    for (int o = 128; o > 0; o >>= 1) {
        if (tid < o) red[tid] = fmaxf(red[tid], red[tid + o]);
        __syncthreads();
    }
    nmax = red[0]; __syncthreads();

    bool anyP = (pmin - MARGIN < nmax);
    bool anyN = (nmax + MARGIN > pmin);
    if (!(anyP && anyN)) {
        if (tid == 0) { d_row_term[i] = 0.0f; d_row_valid[i] = 0.0f; }
        return;
    }

    float m_pos = fmaxf(-ALPHA * (pmin - BASE), 0.0f);
    float m_neg = fmaxf(BETA * (nmax - BASE), 0.0f);

    float sp = 0.0f, sn = 0.0f;
    for (int j8 = tid; j8 < NB / 8; j8 += 256) {
        uint4 sraw = ((const uint4*)srow)[j8];
        int4 la = ((const int4*)slab)[j8 * 2];
        int4 lb = ((const int4*)slab)[j8 * 2 + 1];
        float f[8];
        const __nv_bfloat162* p = (const __nv_bfloat162*)&sraw;
#pragma unroll
        for (int e = 0; e < 4; e++) {
            float2 v = __bfloat1622float2(p[e]);
            f[2 * e] = v.x;
            f[2 * e + 1] = v.y;
        }
        int lv[8] = {la.x, la.y, la.z, la.w, lb.x, lb.y, lb.z, lb.w};
        int j = j8 * 8;
#pragma unroll
        for (int e = 0; e < 8; e++) {
            float s = f[e];
            if (lv[e] == li) {
                if (j + e != i && (s - MARGIN < nmax))
                    sp += expf(-ALPHA * (s - BASE) - m_pos);
            } else {
                if (s + MARGIN > pmin)
                    sn += expf(BETA * (s - BASE) - m_neg);
            }
        }
    }

    red[tid] = sp; __syncthreads();
    for (int o = 128; o > 0; o >>= 1) {
        if (tid < o) red[tid] += red[tid + o];
        __syncthreads();
    }
    sp = red[0]; __syncthreads();
    red[tid] = sn; __syncthreads();
    for (int o = 128; o > 0; o >>= 1) {
        if (tid < o) red[tid] += red[tid + o];
        __syncthreads();
    }
    sn = red[0];

    if (tid == 0) {
        float pt = (logf(expf(-m_pos) + sp) + m_pos) / ALPHA;
        float nt = (logf(expf(-m_neg) + sn) + m_neg) / BETA;
        d_row_term[i] = pt + nt;
        d_row_valid[i] = 1.0f;
    }
}

__global__ void __launch_bounds__(256) final_kernel(float* __restrict__ out) {
    const int tid = threadIdx.x;
    float t = 0.0f, v = 0.0f;
    for (int j = tid; j < NB; j += 256) {
        t += d_row_term[j];
        v += d_row_valid[j];
    }
    __shared__ float rt[256], rv[256];
    rt[tid] = t; rv[tid] = v;
    __syncthreads();
    for (int o = 128; o > 0; o >>= 1) {
        if (tid < o) { rt[tid] += rt[tid + o]; rv[tid] += rv[tid + o]; }
        __syncthreads();
    }
    if (tid == 0) out[0] = rt[0] / fmaxf(rv[0], 1.0f);
}

extern "C" void kernel_launch(void* const* d_in, const int* in_sizes, int n_in,
                              void* d_out, int out_size) {
    const float* emb = (const float*)d_in[0];
    const int* labels = (const int*)d_in[1];
    float* out = (float*)d_out;

    cudaFuncSetAttribute(gemm_kernel, cudaFuncAttributeMaxDynamicSharedMemorySize, SMEM_GEMM);
    cudaFuncSetAttribute(row_kernel, cudaFuncAttributeMaxDynamicSharedMemorySize, 49152);

    round_kernel<<<(NB * ND / 4) / 256, 256>>>(emb);
    gemm_kernel<<<dim3(64, 64), 256, SMEM_GEMM>>>();
    row_kernel<<<NB, 256, 49152>>>(labels);
    final_kernel<<<1, 256>>>(out);
}

// round 6
// speedup vs baseline: 4.8359x; 1.2559x over previous
#include <cuda_runtime.h>
#include <cuda_bf16.h>
#include <math.h>
#include <stdint.h>

#define NB 8192
#define ND 256

__device__ __nv_bfloat16 d_sim[(size_t)NB * NB];    // 128 MB
__device__ __nv_bfloat16 d_embh[(size_t)NB * ND];   // 4 MB
__device__ unsigned short d_lab16[NB];
__device__ unsigned int d_rmin[NB];   // order-preserving encoded fp32, atomicMin
__device__ unsigned int d_rmax[NB];   // atomicMax
__device__ float d_row_term[NB];
__device__ float d_row_valid[NB];

// ---------------- helpers ----------------
__device__ __forceinline__ uint32_t smem_u32(const void* p) {
    uint32_t a;
    asm("{ .reg .u64 t; cvta.to.shared.u64 t, %1; cvt.u32.u64 %0, t; }" : "=r"(a) : "l"(p));
    return a;
}
__device__ __forceinline__ void cp16(uint32_t dst, const void* src) {
    asm volatile("cp.async.cg.shared.global [%0], [%1], 16;" :: "r"(dst), "l"(src) : "memory");
}
__device__ __forceinline__ void cp_commit() {
    asm volatile("cp.async.commit_group;" ::: "memory");
}
template <int N>
__device__ __forceinline__ void cp_wait() {
    asm volatile("cp.async.wait_group %0;" :: "n"(N) : "memory");
}
__device__ __forceinline__ void cp_wait_n(int n) {
    if (n == 0) cp_wait<0>();
    else if (n == 1) cp_wait<1>();
    else cp_wait<2>();
}
__device__ __forceinline__ void ldsm4(uint32_t r[4], uint32_t addr) {
    asm volatile("ldmatrix.sync.aligned.m8n8.x4.shared.b16 {%0,%1,%2,%3}, [%4];"
                 : "=r"(r[0]), "=r"(r[1]), "=r"(r[2]), "=r"(r[3]) : "r"(addr));
}
__device__ __forceinline__ void mma16(float c[4], const uint32_t a[4], uint32_t b0, uint32_t b1) {
    asm volatile(
        "mma.sync.aligned.m16n8k16.row.col.f32.bf16.bf16.f32 "
        "{%0,%1,%2,%3}, {%4,%5,%6,%7}, {%8,%9}, {%0,%1,%2,%3};"
        : "+f"(c[0]), "+f"(c[1]), "+f"(c[2]), "+f"(c[3])
        : "r"(a[0]), "r"(a[1]), "r"(a[2]), "r"(a[3]), "r"(b0), "r"(b1));
}
// order-preserving float <-> uint
__device__ __forceinline__ unsigned int encf(float f) {
    unsigned int u = __float_as_uint(f);
    return (u >> 31) ? ~u : (u | 0x80000000u);
}
__device__ __forceinline__ float decf(unsigned int u) {
    return __uint_as_float((u >> 31) ? (u ^ 0x80000000u) : ~u);
}

// ---------------------------------------------------------------------------
// Prep: emb -> bf16; labels -> u16; init min/max arrays.
// ---------------------------------------------------------------------------
__global__ void __launch_bounds__(256) prep_emb(const float* __restrict__ emb) {
    int i = blockIdx.x * 256 + threadIdx.x;  // 8 floats per thread
    float4 v0 = ((const float4*)emb)[i * 2];
    float4 v1 = ((const float4*)emb)[i * 2 + 1];
    __nv_bfloat162 h[4];
    h[0] = __float22bfloat162_rn(make_float2(v0.x, v0.y));
    h[1] = __float22bfloat162_rn(make_float2(v0.z, v0.w));
    h[2] = __float22bfloat162_rn(make_float2(v1.x, v1.y));
    h[3] = __float22bfloat162_rn(make_float2(v1.z, v1.w));
    ((uint4*)d_embh)[i] = *(uint4*)h;
}
__global__ void __launch_bounds__(256) prep_misc(const int* __restrict__ labels) {
    int i = blockIdx.x * 256 + threadIdx.x;
    d_lab16[i] = (unsigned short)labels[i];
    d_rmin[i] = 0xFFFFFFFFu;  // decodes above +inf
    d_rmax[i] = 0u;           // decodes below -inf
}

// ---------------------------------------------------------------------------
// GEMM: sim = E*E^T, bf16 mma.sync m16n8k16, upper triangle only.
// CTA 128x128, 8 warps (2m x 4n), warp 64x32, BK=64 bf16, 3-stage cp.async.
// Epilogue: bf16 store (direct + transpose) + label-masked min/max atomics.
// ---------------------------------------------------------------------------
#define STG_BYTES 32768
#define SMEM_GEMM 98304

__global__ void __launch_bounds__(256, 2) gemm_kernel(const int* __restrict__ labels) {
    const int bi = blockIdx.y, bj = blockIdx.x;
    if (bj < bi) return;

    extern __shared__ __align__(16) char smem[];
    uint32_t sb = smem_u32(smem);
    const int tid = threadIdx.x, lane = tid & 31, wid = tid >> 5;
    const int mwarp = (wid >> 2) * 64, nwarp = (wid & 3) * 32;
    const int r0 = bi * 128, c0 = bj * 128;
    const __nv_bfloat16* __restrict__ embA = d_embh + (size_t)r0 * ND;
    const __nv_bfloat16* __restrict__ embB = d_embh + (size_t)c0 * ND;

    float acc[4][4][4] = {};

    const int fRow = lane & 15;   // ldmatrix row within 16
    const int fCk = lane >> 4;    // k-half chunk
    const int sw7 = 7;            // swizzle mask

    auto load_stage = [&](int s) {
        uint32_t base = sb + (s % 3) * STG_BYTES;
        int k0 = s * 64;  // bf16 elements
#pragma unroll
        for (int it = 0; it < 4; it++) {  // A: 128 rows x 8 x 16B
            int task = it * 256 + tid;
            int r = task >> 3, c = task & 7;
            cp16(base + r * 128 + ((c ^ (r & sw7)) << 4),
                 embA + (size_t)r * ND + k0 + c * 8);
        }
#pragma unroll
        for (int it = 0; it < 4; it++) {  // B: 128 rows x 8 x 16B
            int task = it * 256 + tid;
            int r = task >> 3, c = task & 7;
            cp16(base + 16384 + r * 128 + ((c ^ (r & sw7)) << 4),
                 embB + (size_t)r * ND + k0 + c * 8);
        }
        cp_commit();
    };

    load_stage(0);
    load_stage(1);
    load_stage(2);

    for (int s = 0; s < 4; s++) {
        int pend = 3 - s;
        cp_wait_n(pend < 2 ? pend : 2);
        __syncthreads();
        uint32_t sA = sb + (s % 3) * STG_BYTES + mwarp * 128;
        uint32_t sB = sb + (s % 3) * STG_BYTES + 16384 + nwarp * 128;
#pragma unroll
        for (int ks = 0; ks < 4; ks++) {  // 4 x k16 = BK 64
            uint32_t a[4][4], b[2][4];
#pragma unroll
            for (int mf = 0; mf < 4; mf++) {
                int row = mf * 16 + fRow;
                ldsm4(a[mf], sA + row * 128 + (((ks * 2 + fCk) ^ (row & 7)) << 4));
            }
#pragma unroll
            for (int nf2 = 0; nf2 < 2; nf2++) {
                int row = nf2 * 16 + fRow;
                ldsm4(b[nf2], sB + row * 128 + (((ks * 2 + fCk) ^ (row & 7)) << 4));
            }
#pragma unroll
            for (int mf = 0; mf < 4; mf++)
#pragma unroll
                for (int nf = 0; nf < 4; nf++)
                    mma16(acc[mf][nf], a[mf], b[nf >> 1][nf & 1], b[nf >> 1][(nf & 1) + 2]);
        }
        __syncthreads();
        if (s + 3 < 4) load_stage(s + 3);
    }

    // Epilogue: fp32 C tile into smem (stride 129), labels into smem.
    float* Cbuf = (float*)smem;                       // 128*129*4 = 66048 B
    int* rlab = (int*)(smem + 66304);                 // 512 B
    int* clab = rlab + 128;
#pragma unroll
    for (int mf = 0; mf < 4; mf++) {
        int rb = mwarp + mf * 16 + (lane >> 2);
#pragma unroll
        for (int nf = 0; nf < 4; nf++) {
            int cb = nwarp + nf * 8 + 2 * (lane & 3);
            Cbuf[rb * 129 + cb] = acc[mf][nf][0];
            Cbuf[rb * 129 + cb + 1] = acc[mf][nf][1];
            Cbuf[(rb + 8) * 129 + cb] = acc[mf][nf][2];
            Cbuf[(rb + 8) * 129 + cb + 1] = acc[mf][nf][3];
        }
    }
    if (tid < 128) rlab[tid] = labels[r0 + tid];
    else clab[tid - 128] = labels[c0 + tid - 128];
    __syncthreads();

    // bf16 stores: direct tile
    for (int idx = tid; idx < 8192; idx += 256) {
        int r = idx >> 6, c2 = (idx & 63) * 2;
        float2 v = make_float2(Cbuf[r * 129 + c2], Cbuf[r * 129 + c2 + 1]);
        *(__nv_bfloat162*)&d_sim[(size_t)(r0 + r) * NB + c0 + c2] = __float22bfloat162_rn(v);
    }
    if (bi != bj) {
        for (int idx = tid; idx < 8192; idx += 256) {
            int rt = idx >> 6, ct2 = (idx & 63) * 2;
            float2 v = make_float2(Cbuf[ct2 * 129 + rt], Cbuf[(ct2 + 1) * 129 + rt]);
            *(__nv_bfloat162*)&d_sim[(size_t)(c0 + rt) * NB + r0 + ct2] = __float22bfloat162_rn(v);
        }
    }

    // Row-side masked min/max: 2 threads per row.
    {
        int r = tid >> 1, half = tid & 1;
        int gi = r0 + r, li = rlab[r];
        float pmin = INFINITY, nmax = -INFINITY;
#pragma unroll 4
        for (int c = half * 64; c < half * 64 + 64; c++) {
            float s = Cbuf[r * 129 + c];
            if (clab[c] == li) {
                if (c0 + c != gi) pmin = fminf(pmin, s);
            } else {
                nmax = fmaxf(nmax, s);
            }
        }
        pmin = fminf(pmin, __shfl_xor_sync(0xFFFFFFFFu, pmin, 1));
        nmax = fmaxf(nmax, __shfl_xor_sync(0xFFFFFFFFu, nmax, 1));
        if (half == 0) {
            if (pmin < INFINITY) atomicMin(&d_rmin[gi], encf(pmin));
            if (nmax > -INFINITY) atomicMax(&d_rmax[gi], encf(nmax));
        }
    }
    // Col-side (transpose contribution): 2 threads per col.
    if (bi != bj) {
        int c = tid >> 1, half = tid & 1;
        int gj = c0 + c, lj = clab[c];
        float pmin = INFINITY, nmax = -INFINITY;
#pragma unroll 4
        for (int r = half * 64; r < half * 64 + 64; r++) {
            float s = Cbuf[r * 129 + c];
            if (rlab[r] == lj) {
                if (r0 + r != gj) pmin = fminf(pmin, s);
            } else {
                nmax = fmaxf(nmax, s);
            }
        }
        pmin = fminf(pmin, __shfl_xor_sync(0xFFFFFFFFu, pmin, 1));
        nmax = fmaxf(nmax, __shfl_xor_sync(0xFFFFFFFFu, nmax, 1));
        if (half == 0) {
            if (pmin < INFINITY) atomicMin(&d_rmin[gj], encf(pmin));
            if (nmax > -INFINITY) atomicMax(&d_rmax[gj], encf(nmax));
        }
    }
}

// ---------------------------------------------------------------------------
// Row kernel: single streaming pass, exp sums with masks from global min/max.
// ---------------------------------------------------------------------------
__global__ void __launch_bounds__(256) row_kernel(float* __restrict__ dummy) {
    const int i = blockIdx.x;
    const int tid = threadIdx.x;
    const int li = d_lab16[i];
    const float ALPHA = 2.0f, BETA = 50.0f, BASE = 0.5f, MARGIN = 0.1f;

    float pmin = decf(d_rmin[i]);
    float nmax = decf(d_rmax[i]);

    bool anyP = (pmin - MARGIN < nmax);
    bool anyN = (nmax + MARGIN > pmin);
    if (!(anyP && anyN)) {
        if (tid == 0) { d_row_term[i] = 0.0f; d_row_valid[i] = 0.0f; }
        return;
    }

    float m_pos = fmaxf(-ALPHA * (pmin - BASE), 0.0f);
    float m_neg = fmaxf(BETA * (nmax - BASE), 0.0f);

    const uint4* __restrict__ rowv = (const uint4*)&d_sim[(size_t)i * NB];
    const uint4* __restrict__ labv = (const uint4*)d_lab16;

    float sp = 0.0f, sn = 0.0f;
    for (int j8 = tid; j8 < NB / 8; j8 += 256) {
        uint4 sraw = rowv[j8];
        uint4 lraw = labv[j8];
        float f[8];
        const __nv_bfloat162* p = (const __nv_bfloat162*)&sraw;
#pragma unroll
        for (int e = 0; e < 4; e++) {
            float2 v = __bfloat1622float2(p[e]);
            f[2 * e] = v.x;
            f[2 * e + 1] = v.y;
        }
        unsigned int lw[4] = {lraw.x, lraw.y, lraw.z, lraw.w};
        int j = j8 * 8;
#pragma unroll
        for (int e = 0; e < 8; e++) {
            int lj = (lw[e >> 1] >> ((e & 1) * 16)) & 0xFFFF;
            float s = f[e];
            if (lj == li) {
                if (j + e != i && (s - MARGIN < nmax))
                    sp += expf(-ALPHA * (s - BASE) - m_pos);
            } else {
                if (s + MARGIN > pmin)
                    sn += expf(BETA * (s - BASE) - m_neg);
            }
        }
    }

    __shared__ float red[256];
    red[tid] = sp; __syncthreads();
    for (int o = 128; o > 0; o >>= 1) {
        if (tid < o) red[tid] += red[tid + o];
        __syncthreads();
    }
    sp = red[0]; __syncthreads();
    red[tid] = sn; __syncthreads();
    for (int o = 128; o > 0; o >>= 1) {
        if (tid < o) red[tid] += red[tid + o];
        __syncthreads();
    }
    sn = red[0];

    if (tid == 0) {
        float pt = (logf(expf(-m_pos) + sp) + m_pos) / ALPHA;
        float nt = (logf(expf(-m_neg) + sn) + m_neg) / BETA;
        d_row_term[i] = pt + nt;
        d_row_valid[i] = 1.0f;
    }
}

__global__ void __launch_bounds__(1024) final_kernel(float* __restrict__ out) {
    const int tid = threadIdx.x;
    float t = 0.0f, v = 0.0f;
    for (int j = tid; j < NB; j += 1024) {
        t += d_row_term[j];
        v += d_row_valid[j];
    }
    __shared__ float rt[1024], rv[1024];
    rt[tid] = t; rv[tid] = v;
    __syncthreads();
    for (int o = 512; o > 0; o >>= 1) {
        if (tid < o) { rt[tid] += rt[tid + o]; rv[tid] += rv[tid + o]; }
        __syncthreads();
    }
    if (tid == 0) out[0] = rt[0] / fmaxf(rv[0], 1.0f);
}

extern "C" void kernel_launch(void* const* d_in, const int* in_sizes, int n_in,
                              void* d_out, int out_size) {
    const float* emb = (const float*)d_in[0];
    const int* labels = (const int*)d_in[1];
    float* out = (float*)d_out;

    cudaFuncSetAttribute(gemm_kernel, cudaFuncAttributeMaxDynamicSharedMemorySize, SMEM_GEMM);

    prep_emb<<<(NB * ND / 8) / 256, 256>>>(emb);
    prep_misc<<<NB / 256, 256>>>(labels);
    gemm_kernel<<<dim3(64, 64), 256, SMEM_GEMM>>>(labels);
    row_kernel<<<NB, 256>>>(nullptr);
    final_kernel<<<1, 1024>>>(out);
}

// round 7
// speedup vs baseline: 5.2466x; 1.0849x over previous
#include <cuda_runtime.h>
#include <cuda_fp16.h>
#include <cuda_bf16.h>
#include <math.h>
#include <stdint.h>

#define NB 8192
#define ND 256

__device__ __nv_bfloat16 d_sim[(size_t)NB * NB];    // 128 MB
__device__ __half d_embh[(size_t)NB * ND];          // 4 MB
__device__ unsigned short d_lab16[NB];
__device__ unsigned int d_rmin[NB];   // order-preserving encoded fp32, atomicMin
__device__ unsigned int d_rmax[NB];   // atomicMax
__device__ float d_row_term[NB];
__device__ float d_row_valid[NB];

// ---------------- helpers ----------------
__device__ __forceinline__ uint32_t smem_u32(const void* p) {
    uint32_t a;
    asm("{ .reg .u64 t; cvta.to.shared.u64 t, %1; cvt.u32.u64 %0, t; }" : "=r"(a) : "l"(p));
    return a;
}
__device__ __forceinline__ void cp16(uint32_t dst, const void* src) {
    asm volatile("cp.async.cg.shared.global [%0], [%1], 16;" :: "r"(dst), "l"(src) : "memory");
}
__device__ __forceinline__ void cp_commit() {
    asm volatile("cp.async.commit_group;" ::: "memory");
}
template <int N>
__device__ __forceinline__ void cp_wait() {
    asm volatile("cp.async.wait_group %0;" :: "n"(N) : "memory");
}
__device__ __forceinline__ void cp_wait_n(int n) {
    if (n == 0) cp_wait<0>();
    else if (n == 1) cp_wait<1>();
    else cp_wait<2>();
}
__device__ __forceinline__ void ldsm4(uint32_t r[4], uint32_t addr) {
    asm volatile("ldmatrix.sync.aligned.m8n8.x4.shared.b16 {%0,%1,%2,%3}, [%4];"
                 : "=r"(r[0]), "=r"(r[1]), "=r"(r[2]), "=r"(r[3]) : "r"(addr));
}
// f16 x f16 -> f16 accumulate MMA
__device__ __forceinline__ void mma16h(uint32_t c[2], const uint32_t a[4], uint32_t b0, uint32_t b1) {
    asm volatile(
        "mma.sync.aligned.m16n8k16.row.col.f16.f16.f16.f16 "
        "{%0,%1}, {%2,%3,%4,%5}, {%6,%7}, {%0,%1};"
        : "+r"(c[0]), "+r"(c[1])
        : "r"(a[0]), "r"(a[1]), "r"(a[2]), "r"(a[3]), "r"(b0), "r"(b1));
}
__device__ __forceinline__ float ex2(float x) {
    float r;
    asm("ex2.approx.f32 %0, %1;" : "=f"(r) : "f"(x));
    return r;
}
// order-preserving float <-> uint
__device__ __forceinline__ unsigned int encf(float f) {
    unsigned int u = __float_as_uint(f);
    return (u >> 31) ? ~u : (u | 0x80000000u);
}
__device__ __forceinline__ float decf(unsigned int u) {
    return __uint_as_float((u >> 31) ? (u ^ 0x80000000u) : ~u);
}

// ---------------------------------------------------------------------------
// Prep: emb -> f16; labels -> u16; init min/max arrays.
// ---------------------------------------------------------------------------
__global__ void __launch_bounds__(256) prep_emb(const float* __restrict__ emb) {
    int i = blockIdx.x * 256 + threadIdx.x;  // 8 floats per thread
    float4 v0 = ((const float4*)emb)[i * 2];
    float4 v1 = ((const float4*)emb)[i * 2 + 1];
    __half2 h[4];
    h[0] = __float22half2_rn(make_float2(v0.x, v0.y));
    h[1] = __float22half2_rn(make_float2(v0.z, v0.w));
    h[2] = __float22half2_rn(make_float2(v1.x, v1.y));
    h[3] = __float22half2_rn(make_float2(v1.z, v1.w));
    ((uint4*)d_embh)[i] = *(uint4*)h;
}
__global__ void __launch_bounds__(256) prep_misc(const int* __restrict__ labels) {
    int i = blockIdx.x * 256 + threadIdx.x;
    d_lab16[i] = (unsigned short)labels[i];
    d_rmin[i] = 0xFFFFFFFFu;
    d_rmax[i] = 0u;
}

// ---------------------------------------------------------------------------
// GEMM: sim = E*E^T, f16 mma.sync (f16 accum), upper triangle only.
// CTA 128x128, 8 warps (2m x 4n), warp 64x32, BK=64 f16, 3-stage cp.async.
// Epilogue: bf16 store (direct + transpose) + label-masked min/max atomics.
// ---------------------------------------------------------------------------
#define STG_BYTES 32768
#define SMEM_GEMM 98304

__global__ void __launch_bounds__(256, 2) gemm_kernel(const int* __restrict__ labels) {
    const int bi = blockIdx.y, bj = blockIdx.x;
    if (bj < bi) return;

    extern __shared__ __align__(16) char smem[];
    uint32_t sb = smem_u32(smem);
    const int tid = threadIdx.x, lane = tid & 31, wid = tid >> 5;
    const int mwarp = (wid >> 2) * 64, nwarp = (wid & 3) * 32;
    const int r0 = bi * 128, c0 = bj * 128;
    const __half* __restrict__ embA = d_embh + (size_t)r0 * ND;
    const __half* __restrict__ embB = d_embh + (size_t)c0 * ND;

    uint32_t acc[4][4][2] = {};   // packed half2 accumulators

    const int fRow = lane & 15;
    const int fCk = lane >> 4;

    auto load_stage = [&](int s) {
        uint32_t base = sb + (s % 3) * STG_BYTES;
        int k0 = s * 64;
#pragma unroll
        for (int it = 0; it < 4; it++) {
            int task = it * 256 + tid;
            int r = task >> 3, c = task & 7;
            cp16(base + r * 128 + ((c ^ (r & 7)) << 4),
                 embA + (size_t)r * ND + k0 + c * 8);
        }
#pragma unroll
        for (int it = 0; it < 4; it++) {
            int task = it * 256 + tid;
            int r = task >> 3, c = task & 7;
            cp16(base + 16384 + r * 128 + ((c ^ (r & 7)) << 4),
                 embB + (size_t)r * ND + k0 + c * 8);
        }
        cp_commit();
    };

    load_stage(0);
    load_stage(1);
    load_stage(2);

    for (int s = 0; s < 4; s++) {
        int pend = 3 - s;
        cp_wait_n(pend < 2 ? pend : 2);
        __syncthreads();
        uint32_t sA = sb + (s % 3) * STG_BYTES + mwarp * 128;
        uint32_t sB = sb + (s % 3) * STG_BYTES + 16384 + nwarp * 128;
#pragma unroll
        for (int ks = 0; ks < 4; ks++) {
            uint32_t a[4][4], b[2][4];
#pragma unroll
            for (int mf = 0; mf < 4; mf++) {
                int row = mf * 16 + fRow;
                ldsm4(a[mf], sA + row * 128 + (((ks * 2 + fCk) ^ (row & 7)) << 4));
            }
#pragma unroll
            for (int nf2 = 0; nf2 < 2; nf2++) {
                int row = nf2 * 16 + fRow;
                ldsm4(b[nf2], sB + row * 128 + (((ks * 2 + fCk) ^ (row & 7)) << 4));
            }
#pragma unroll
            for (int mf = 0; mf < 4; mf++)
#pragma unroll
                for (int nf = 0; nf < 4; nf++)
                    mma16h(acc[mf][nf], a[mf], b[nf >> 1][nf & 1], b[nf >> 1][(nf & 1) + 2]);
        }
        __syncthreads();
        if (s + 3 < 4) load_stage(s + 3);
    }

    // Epilogue: fp32 C tile into smem (stride 129), labels into smem.
    float* Cbuf = (float*)smem;                 // 66048 B
    int* rlab = (int*)(smem + 66304);
    int* clab = rlab + 128;
#pragma unroll
    for (int mf = 0; mf < 4; mf++) {
        int rb = mwarp + mf * 16 + (lane >> 2);
#pragma unroll
        for (int nf = 0; nf < 4; nf++) {
            int cb = nwarp + nf * 8 + 2 * (lane & 3);
            float2 v0 = __half22float2(*(__half2*)&acc[mf][nf][0]);
            float2 v1 = __half22float2(*(__half2*)&acc[mf][nf][1]);
            Cbuf[rb * 129 + cb] = v0.x;
            Cbuf[rb * 129 + cb + 1] = v0.y;
            Cbuf[(rb + 8) * 129 + cb] = v1.x;
            Cbuf[(rb + 8) * 129 + cb + 1] = v1.y;
        }
    }
    if (tid < 128) rlab[tid] = labels[r0 + tid];
    else clab[tid - 128] = labels[c0 + tid - 128];
    __syncthreads();

    for (int idx = tid; idx < 8192; idx += 256) {
        int r = idx >> 6, c2 = (idx & 63) * 2;
        float2 v = make_float2(Cbuf[r * 129 + c2], Cbuf[r * 129 + c2 + 1]);
        *(__nv_bfloat162*)&d_sim[(size_t)(r0 + r) * NB + c0 + c2] = __float22bfloat162_rn(v);
    }
    if (bi != bj) {
        for (int idx = tid; idx < 8192; idx += 256) {
            int rt = idx >> 6, ct2 = (idx & 63) * 2;
            float2 v = make_float2(Cbuf[ct2 * 129 + rt], Cbuf[(ct2 + 1) * 129 + rt]);
            *(__nv_bfloat162*)&d_sim[(size_t)(c0 + rt) * NB + r0 + ct2] = __float22bfloat162_rn(v);
        }
    }

    // Row-side masked min/max: 2 threads per row.
    {
        int r = tid >> 1, half = tid & 1;
        int gi = r0 + r, li = rlab[r];
        float pmin = INFINITY, nmax = -INFINITY;
#pragma unroll 4
        for (int c = half * 64; c < half * 64 + 64; c++) {
            float s = Cbuf[r * 129 + c];
            if (clab[c] == li) {
                if (c0 + c != gi) pmin = fminf(pmin, s);
            } else {
                nmax = fmaxf(nmax, s);
            }
        }
        pmin = fminf(pmin, __shfl_xor_sync(0xFFFFFFFFu, pmin, 1));
        nmax = fmaxf(nmax, __shfl_xor_sync(0xFFFFFFFFu, nmax, 1));
        if (half == 0) {
            if (pmin < INFINITY) atomicMin(&d_rmin[gi], encf(pmin));
            if (nmax > -INFINITY) atomicMax(&d_rmax[gi], encf(nmax));
        }
    }
    // Col-side (transpose contribution).
    if (bi != bj) {
        int c = tid >> 1, half = tid & 1;
        int gj = c0 + c, lj = clab[c];
        float pmin = INFINITY, nmax = -INFINITY;
#pragma unroll 4
        for (int r = half * 64; r < half * 64 + 64; r++) {
            float s = Cbuf[r * 129 + c];
            if (rlab[r] == lj) {
                if (r0 + r != gj) pmin = fminf(pmin, s);
            } else {
                nmax = fmaxf(nmax, s);
            }
        }
        pmin = fminf(pmin, __shfl_xor_sync(0xFFFFFFFFu, pmin, 1));
        nmax = fmaxf(nmax, __shfl_xor_sync(0xFFFFFFFFu, nmax, 1));
        if (half == 0) {
            if (pmin < INFINITY) atomicMin(&d_rmin[gj], encf(pmin));
            if (nmax > -INFINITY) atomicMax(&d_rmax[gj], encf(nmax));
        }
    }
}

// ---------------------------------------------------------------------------
// Row kernel: single streaming pass. Hot path = raw ex2 with folded constants;
// rare label-matches (positives + self) via mask-aggregated cold branch.
// ---------------------------------------------------------------------------
__global__ void __launch_bounds__(256) row_kernel() {
    const int i = blockIdx.x;
    const int tid = threadIdx.x;
    const float ALPHA = 2.0f, BETA = 50.0f, BASE = 0.5f, MARGIN = 0.1f;
    const float L2E = 1.44269504f;

    const unsigned li = d_lab16[i];
    float pmin = decf(d_rmin[i]);
    float nmax = decf(d_rmax[i]);

    bool anyP = (pmin - MARGIN < nmax);
    bool anyN = (nmax + MARGIN > pmin);
    if (!(anyP && anyN)) {
        if (tid == 0) { d_row_term[i] = 0.0f; d_row_valid[i] = 0.0f; }
        return;
    }

    float m_pos = fmaxf(-ALPHA * (pmin - BASE), 0.0f);
    float m_neg = fmaxf(BETA * (nmax - BASE), 0.0f);

    // hot-path constants: 2^(kn1*s + kn0) = exp(BETA*(s-BASE) - m_neg)
    const float kn1 = BETA * L2E;
    const float kn0 = (-BETA * BASE - m_neg) * L2E;
    const float kp1 = -ALPHA * L2E;
    const float kp0 = (ALPHA * BASE - m_pos) * L2E;
    const float thrN = pmin - MARGIN;   // neg included if s > thrN
    const float thrP = nmax + MARGIN;   // pos included if s < thrP

    const uint4* __restrict__ rowv = (const uint4*)&d_sim[(size_t)i * NB];
    const uint4* __restrict__ labv = (const uint4*)d_lab16;

    float sp = 0.0f, sn = 0.0f;
#pragma unroll 2
    for (int j8 = tid; j8 < NB / 8; j8 += 256) {
        uint4 sraw = rowv[j8];
        uint4 lraw = labv[j8];
        float f[8];
        const __nv_bfloat162* p = (const __nv_bfloat162*)&sraw;
#pragma unroll
        for (int e = 0; e < 4; e++) {
            float2 v = __bfloat1622float2(p[e]);
            f[2 * e] = v.x;
            f[2 * e + 1] = v.y;
        }
        unsigned lw[4] = {lraw.x, lraw.y, lraw.z, lraw.w};
        unsigned mm = 0;
#pragma unroll
        for (int e = 0; e < 8; e++) {
            unsigned lv = (lw[e >> 1] >> ((e & 1) * 16)) & 0xFFFFu;
            bool match = (lv == li);
            mm |= ((unsigned)match) << e;
            float ex = ex2(fmaf(kn1, f[e], kn0));
            if (!match && f[e] > thrN) sn += ex;
        }
        if (mm) {   // rare: positives + self
            int j = j8 * 8;
#pragma unroll
            for (int e = 0; e < 8; e++) {
                if ((mm >> e) & 1) {
                    if (j + e != i && f[e] < thrP)
                        sp += ex2(fmaf(kp1, f[e], kp0));
                }
            }
        }
    }

    __shared__ float red[256];
    red[tid] = sp; __syncthreads();
    for (int o = 128; o > 0; o >>= 1) {
        if (tid < o) red[tid] += red[tid + o];
        __syncthreads();
    }
    sp = red[0]; __syncthreads();
    red[tid] = sn; __syncthreads();
    for (int o = 128; o > 0; o >>= 1) {
        if (tid < o) red[tid] += red[tid + o];
        __syncthreads();
    }
    sn = red[0];

    if (tid == 0) {
        float pt = (logf(expf(-m_pos) + sp) + m_pos) / ALPHA;
        float nt = (logf(expf(-m_neg) + sn) + m_neg) / BETA;
        d_row_term[i] = pt + nt;
        d_row_valid[i] = 1.0f;
    }
}

__global__ void __launch_bounds__(1024) final_kernel(float* __restrict__ out) {
    const int tid = threadIdx.x;
    float t = 0.0f, v = 0.0f;
    for (int j = tid; j < NB; j += 1024) {
        t += d_row_term[j];
        v += d_row_valid[j];
    }
    __shared__ float rt[1024], rv[1024];
    rt[tid] = t; rv[tid] = v;
    __syncthreads();
    for (int o = 512; o > 0; o >>= 1) {
        if (tid < o) { rt[tid] += rt[tid + o]; rv[tid] += rv[tid + o]; }
        __syncthreads();
    }
    if (tid == 0) out[0] = rt[0] / fmaxf(rv[0], 1.0f);
}

extern "C" void kernel_launch(void* const* d_in, const int* in_sizes, int n_in,
                              void* d_out, int out_size) {
    const float* emb = (const float*)d_in[0];
    const int* labels = (const int*)d_in[1];
    float* out = (float*)d_out;

    cudaFuncSetAttribute(gemm_kernel, cudaFuncAttributeMaxDynamicSharedMemorySize, SMEM_GEMM);

    prep_emb<<<(NB * ND / 8) / 256, 256>>>(emb);
    prep_misc<<<NB / 256, 256>>>(labels);
    gemm_kernel<<<dim3(64, 64), 256, SMEM_GEMM>>>(labels);
    row_kernel<<<NB, 256>>>();
    final_kernel<<<1, 1024>>>(out);
}

// round 8
// speedup vs baseline: 5.3193x; 1.0139x over previous
#include <cuda_runtime.h>
#include <cuda_fp16.h>
#include <math.h>
#include <stdint.h>

#define NB 8192
#define ND 256
#define NCLS 1024

__device__ __half d_sim[(size_t)NB * NB];      // 128 MB, f16
__device__ __half d_embh[(size_t)NB * ND];     // 4 MB
__device__ unsigned short d_lab16[NB];
__device__ int d_cls_start[NCLS + 1];
__device__ int d_cls_items[NB];
__device__ unsigned int d_rmin[NB];   // order-preserving encoded fp32
__device__ unsigned int d_rmax[NB];
__device__ float d_row_term[NB];
__device__ float d_row_valid[NB];

// ---------------- helpers ----------------
__device__ __forceinline__ uint32_t smem_u32(const void* p) {
    uint32_t a;
    asm("{ .reg .u64 t; cvta.to.shared.u64 t, %1; cvt.u32.u64 %0, t; }" : "=r"(a) : "l"(p));
    return a;
}
__device__ __forceinline__ void cp16(uint32_t dst, const void* src) {
    asm volatile("cp.async.cg.shared.global [%0], [%1], 16;" :: "r"(dst), "l"(src) : "memory");
}
__device__ __forceinline__ void cp_commit() {
    asm volatile("cp.async.commit_group;" ::: "memory");
}
template <int N>
__device__ __forceinline__ void cp_wait() {
    asm volatile("cp.async.wait_group %0;" :: "n"(N) : "memory");
}
__device__ __forceinline__ void cp_wait_n(int n) {
    if (n == 0) cp_wait<0>();
    else if (n == 1) cp_wait<1>();
    else cp_wait<2>();
}
__device__ __forceinline__ void ldsm4(uint32_t r[4], uint32_t addr) {
    asm volatile("ldmatrix.sync.aligned.m8n8.x4.shared.b16 {%0,%1,%2,%3}, [%4];"
                 : "=r"(r[0]), "=r"(r[1]), "=r"(r[2]), "=r"(r[3]) : "r"(addr));
}
__device__ __forceinline__ void mma16h(uint32_t c[2], const uint32_t a[4], uint32_t b0, uint32_t b1) {
    asm volatile(
        "mma.sync.aligned.m16n8k16.row.col.f16.f16.f16.f16 "
        "{%0,%1}, {%2,%3,%4,%5}, {%6,%7}, {%0,%1};"
        : "+r"(c[0]), "+r"(c[1])
        : "r"(a[0]), "r"(a[1]), "r"(a[2]), "r"(a[3]), "r"(b0), "r"(b1));
}
__device__ __forceinline__ float ex2(float x) {
    float r;
    asm("ex2.approx.f32 %0, %1;" : "=f"(r) : "f"(x));
    return r;
}
__device__ __forceinline__ unsigned int encf(float f) {
    unsigned int u = __float_as_uint(f);
    return (u >> 31) ? ~u : (u | 0x80000000u);
}
__device__ __forceinline__ float decf(unsigned int u) {
    return __uint_as_float((u >> 31) ? (u ^ 0x80000000u) : ~u);
}

// ---------------------------------------------------------------------------
// Prep kernels
// ---------------------------------------------------------------------------
__global__ void __launch_bounds__(256) prep_emb(const float* __restrict__ emb) {
    int i = blockIdx.x * 256 + threadIdx.x;
    float4 v0 = ((const float4*)emb)[i * 2];
    float4 v1 = ((const float4*)emb)[i * 2 + 1];
    __half2 h[4];
    h[0] = __float22half2_rn(make_float2(v0.x, v0.y));
    h[1] = __float22half2_rn(make_float2(v0.z, v0.w));
    h[2] = __float22half2_rn(make_float2(v1.x, v1.y));
    h[3] = __float22half2_rn(make_float2(v1.z, v1.w));
    ((uint4*)d_embh)[i] = *(uint4*)h;
}
__global__ void __launch_bounds__(256) prep_misc(const int* __restrict__ labels) {
    int i = blockIdx.x * 256 + threadIdx.x;
    d_lab16[i] = (unsigned short)labels[i];
    d_rmin[i] = 0xFFFFFFFFu;
    d_rmax[i] = 0u;
}
// single block, 1024 threads: per-class index lists (deterministic: sorted)
__global__ void __launch_bounds__(1024) prep_cls(const int* __restrict__ labels) {
    __shared__ int cnt[NCLS];
    __shared__ int sc[NCLS];
    __shared__ int ofs[NCLS];
    int t = threadIdx.x;
    cnt[t] = 0;
    __syncthreads();
    for (int j = t; j < NB; j += 1024) atomicAdd(&cnt[labels[j]], 1);
    __syncthreads();
    sc[t] = cnt[t];
    __syncthreads();
    for (int d = 1; d < NCLS; d <<= 1) {
        int v = (t >= d) ? sc[t - d] : 0;
        __syncthreads();
        sc[t] += v;
        __syncthreads();
    }
    int excl = sc[t] - cnt[t];
    d_cls_start[t] = excl;
    if (t == NCLS - 1) d_cls_start[NCLS] = NB;
    ofs[t] = excl;
    __syncthreads();
    for (int j = t; j < NB; j += 1024) {
        int p = atomicAdd(&ofs[labels[j]], 1);
        d_cls_items[p] = j;
    }
    __syncthreads();
    // insertion-sort own class list -> deterministic content
    int s0 = excl, e0 = excl + cnt[t];
    for (int a = s0 + 1; a < e0; a++) {
        int key = d_cls_items[a];
        int b = a - 1;
        while (b >= s0 && d_cls_items[b] > key) {
            d_cls_items[b + 1] = d_cls_items[b];
            b--;
        }
        d_cls_items[b + 1] = key;
    }
}

// ---------------------------------------------------------------------------
// GEMM: sim = E*E^T, f16 mma.sync (f16 accum), upper triangle only.
// CTA 128x128, 8 warps, warp 64x32, BK=64, 3-stage cp.async,
// fragment double-buffering inside each stage.
// ---------------------------------------------------------------------------
#define STG_BYTES 32768
#define SMEM_GEMM 98304

__global__ void __launch_bounds__(256, 2) gemm_kernel(const int* __restrict__ labels) {
    const int bi = blockIdx.y, bj = blockIdx.x;
    if (bj < bi) return;

    extern __shared__ __align__(16) char smem[];
    uint32_t sb = smem_u32(smem);
    const int tid = threadIdx.x, lane = tid & 31, wid = tid >> 5;
    const int mwarp = (wid >> 2) * 64, nwarp = (wid & 3) * 32;
    const int r0 = bi * 128, c0 = bj * 128;
    const __half* __restrict__ embA = d_embh + (size_t)r0 * ND;
    const __half* __restrict__ embB = d_embh + (size_t)c0 * ND;

    uint32_t acc[4][4][2] = {};
    const int fRow = lane & 15;
    const int fCk = lane >> 4;

    auto load_stage = [&](int s) {
        uint32_t base = sb + (s % 3) * STG_BYTES;
        int k0 = s * 64;
#pragma unroll
        for (int it = 0; it < 4; it++) {
            int task = it * 256 + tid;
            int r = task >> 3, c = task & 7;
            cp16(base + r * 128 + ((c ^ (r & 7)) << 4),
                 embA + (size_t)r * ND + k0 + c * 8);
        }
#pragma unroll
        for (int it = 0; it < 4; it++) {
            int task = it * 256 + tid;
            int r = task >> 3, c = task & 7;
            cp16(base + 16384 + r * 128 + ((c ^ (r & 7)) << 4),
                 embB + (size_t)r * ND + k0 + c * 8);
        }
        cp_commit();
    };

    load_stage(0);
    load_stage(1);
    load_stage(2);

    for (int s = 0; s < 4; s++) {
        int pend = 3 - s;
        cp_wait_n(pend < 2 ? pend : 2);
        __syncthreads();
        uint32_t sA = sb + (s % 3) * STG_BYTES + mwarp * 128;
        uint32_t sB = sb + (s % 3) * STG_BYTES + 16384 + nwarp * 128;

        uint32_t a[2][4][4], b[2][2][4];
        auto ldfrag = [&](int ks, int buf) {
#pragma unroll
            for (int mf = 0; mf < 4; mf++) {
                int row = mf * 16 + fRow;
                ldsm4(a[buf][mf], sA + row * 128 + (((ks * 2 + fCk) ^ (row & 7)) << 4));
            }
#pragma unroll
            for (int nf2 = 0; nf2 < 2; nf2++) {
                int row = nf2 * 16 + fRow;
                ldsm4(b[buf][nf2], sB + row * 128 + (((ks * 2 + fCk) ^ (row & 7)) << 4));
            }
        };
        ldfrag(0, 0);
#pragma unroll
        for (int ks = 0; ks < 4; ks++) {
            int cur = ks & 1;
            if (ks < 3) ldfrag(ks + 1, cur ^ 1);
#pragma unroll
            for (int mf = 0; mf < 4; mf++)
#pragma unroll
                for (int nf = 0; nf < 4; nf++)
                    mma16h(acc[mf][nf], a[cur][mf],
                           b[cur][nf >> 1][nf & 1], b[cur][nf >> 1][(nf & 1) + 2]);
        }
        __syncthreads();
        if (s + 3 < 4) load_stage(s + 3);
    }

    // Epilogue: fp32 C tile in smem (stride 129), labels in smem.
    float* Cbuf = (float*)smem;
    int* rlab = (int*)(smem + 66304);
    int* clab = rlab + 128;
#pragma unroll
    for (int mf = 0; mf < 4; mf++) {
        int rb = mwarp + mf * 16 + (lane >> 2);
#pragma unroll
        for (int nf = 0; nf < 4; nf++) {
            int cb = nwarp + nf * 8 + 2 * (lane & 3);
            float2 v0 = __half22float2(*(__half2*)&acc[mf][nf][0]);
            float2 v1 = __half22float2(*(__half2*)&acc[mf][nf][1]);
            Cbuf[rb * 129 + cb] = v0.x;
            Cbuf[rb * 129 + cb + 1] = v0.y;
            Cbuf[(rb + 8) * 129 + cb] = v1.x;
            Cbuf[(rb + 8) * 129 + cb + 1] = v1.y;
        }
    }
    if (tid < 128) rlab[tid] = labels[r0 + tid];
    else clab[tid - 128] = labels[c0 + tid - 128];
    __syncthreads();

    for (int idx = tid; idx < 8192; idx += 256) {
        int r = idx >> 6, c2 = (idx & 63) * 2;
        float2 v = make_float2(Cbuf[r * 129 + c2], Cbuf[r * 129 + c2 + 1]);
        *(__half2*)&d_sim[(size_t)(r0 + r) * NB + c0 + c2] = __float22half2_rn(v);
    }
    if (bi != bj) {
        for (int idx = tid; idx < 8192; idx += 256) {
            int rt = idx >> 6, ct2 = (idx & 63) * 2;
            float2 v = make_float2(Cbuf[ct2 * 129 + rt], Cbuf[(ct2 + 1) * 129 + rt]);
            *(__half2*)&d_sim[(size_t)(c0 + rt) * NB + r0 + ct2] = __float22half2_rn(v);
        }
    }

    // Row-side masked min/max.
    {
        int r = tid >> 1, half = tid & 1;
        int gi = r0 + r, li = rlab[r];
        float pmin = INFINITY, nmax = -INFINITY;
#pragma unroll 4
        for (int c = half * 64; c < half * 64 + 64; c++) {
            float s = Cbuf[r * 129 + c];
            if (clab[c] == li) {
                if (c0 + c != gi) pmin = fminf(pmin, s);
            } else {
                nmax = fmaxf(nmax, s);
            }
        }
        pmin = fminf(pmin, __shfl_xor_sync(0xFFFFFFFFu, pmin, 1));
        nmax = fmaxf(nmax, __shfl_xor_sync(0xFFFFFFFFu, nmax, 1));
        if (half == 0) {
            if (pmin < INFINITY) atomicMin(&d_rmin[gi], encf(pmin));
            if (nmax > -INFINITY) atomicMax(&d_rmax[gi], encf(nmax));
        }
    }
    if (bi != bj) {
        int c = tid >> 1, half = tid & 1;
        int gj = c0 + c, lj = clab[c];
        float pmin = INFINITY, nmax = -INFINITY;
#pragma unroll 4
        for (int r = half * 64; r < half * 64 + 64; r++) {
            float s = Cbuf[r * 129 + c];
            if (rlab[r] == lj) {
                if (r0 + r != gj) pmin = fminf(pmin, s);
            } else {
                nmax = fmaxf(nmax, s);
            }
        }
        pmin = fminf(pmin, __shfl_xor_sync(0xFFFFFFFFu, pmin, 1));
        nmax = fmaxf(nmax, __shfl_xor_sync(0xFFFFFFFFu, nmax, 1));
        if (half == 0) {
            if (pmin < INFINITY) atomicMin(&d_rmin[gj], encf(pmin));
            if (nmax > -INFINITY) atomicMax(&d_rmax[gj], encf(nmax));
        }
    }
}

// ---------------------------------------------------------------------------
// Row kernel: label-free hot loop with provable exp-drop threshold;
// rare above-cut elements take exact cold path; positives from class list.
// ---------------------------------------------------------------------------
__global__ void __launch_bounds__(256) row_kernel() {
    const int i = blockIdx.x;
    const int tid = threadIdx.x;
    const float ALPHA = 2.0f, BETA = 50.0f, BASE = 0.5f, MARGIN = 0.1f;
    const float L2E = 1.44269504f;

    const unsigned li = d_lab16[i];
    float pmin = decf(d_rmin[i]);
    float nmax = decf(d_rmax[i]);

    bool anyP = (pmin - MARGIN < nmax);
    bool anyN = (nmax + MARGIN > pmin);
    if (!(anyP && anyN)) {
        if (tid == 0) { d_row_term[i] = 0.0f; d_row_valid[i] = 0.0f; }
        return;
    }

    float m_pos = fmaxf(-ALPHA * (pmin - BASE), 0.0f);
    float m_neg = fmaxf(BETA * (nmax - BASE), 0.0f);

    const float kn1 = BETA * L2E;
    const float kn0 = (-BETA * BASE - m_neg) * L2E;
    const float kp1 = -ALPHA * L2E;
    const float kp0 = (ALPHA * BASE - m_pos) * L2E;
    const float thrN = pmin - MARGIN;
    const float thrP = nmax + MARGIN;
    // drop negatives with exponent < -14 after shift: total drop <= 8192*e^-14
    const float scut = BASE + (m_neg - 14.0f) * (1.0f / BETA);
    const __half scut_h = __float2half_rd(scut);

    const uint4* __restrict__ rowv = (const uint4*)&d_sim[(size_t)i * NB];

    float sn = 0.0f, sp = 0.0f;
    uint4 v[4];
#pragma unroll
    for (int t = 0; t < 4; t++) v[t] = rowv[tid + t * 256];
#pragma unroll
    for (int t = 0; t < 4; t++) {
        const __half2* hp = (const __half2*)&v[t];
        __half2 m01 = __hmax2(hp[0], hp[1]);
        __half2 m23 = __hmax2(hp[2], hp[3]);
        __half2 m = __hmax2(m01, m23);
        __half hm = __hmax(__low2half(m), __high2half(m));
        if (__hgt(hm, scut_h)) {
            int j0 = (tid + t * 256) * 8;
            const __half* he = (const __half*)&v[t];
#pragma unroll
            for (int e = 0; e < 8; e++) {
                float s = __half2float(he[e]);
                if (s > scut) {
                    int j = j0 + e;
                    if ((unsigned)d_lab16[j] != li) {
                        if (s > thrN) sn += ex2(fmaf(kn1, s, kn0));
                    }
                }
            }
        }
    }

    // positives (exact): class index list
    {
        int cs = d_cls_start[li], ce = d_cls_start[li + 1];
        for (int p = cs + tid; p < ce; p += 256) {
            int j = d_cls_items[p];
            if (j != i) {
                float s = __half2float(d_sim[(size_t)i * NB + j]);
                if (s < thrP) sp += ex2(fmaf(kp1, s, kp0));
            }
        }
    }

    __shared__ float red[256];
    red[tid] = sp; __syncthreads();
    for (int o = 128; o > 0; o >>= 1) {
        if (tid < o) red[tid] += red[tid + o];
        __syncthreads();
    }
    sp = red[0]; __syncthreads();
    red[tid] = sn; __syncthreads();
    for (int o = 128; o > 0; o >>= 1) {
        if (tid < o) red[tid] += red[tid + o];
        __syncthreads();
    }
    sn = red[0];

    if (tid == 0) {
        float pt = (logf(expf(-m_pos) + sp) + m_pos) / ALPHA;
        float nt = (logf(expf(-m_neg) + sn) + m_neg) / BETA;
        d_row_term[i] = pt + nt;
        d_row_valid[i] = 1.0f;
    }
}

__global__ void __launch_bounds__(1024) final_kernel(float* __restrict__ out) {
    const int tid = threadIdx.x;
    float t = 0.0f, v = 0.0f;
    for (int j = tid; j < NB; j += 1024) {
        t += d_row_term[j];
        v += d_row_valid[j];
    }
    __shared__ float rt[1024], rv[1024];
    rt[tid] = t; rv[tid] = v;
    __syncthreads();
    for (int o = 512; o > 0; o >>= 1) {
        if (tid < o) { rt[tid] += rt[tid + o]; rv[tid] += rv[tid + o]; }
        __syncthreads();
    }
    if (tid == 0) out[0] = rt[0] / fmaxf(rv[0], 1.0f);
}

extern "C" void kernel_launch(void* const* d_in, const int* in_sizes, int n_in,
                              void* d_out, int out_size) {
    const float* emb = (const float*)d_in[0];
    const int* labels = (const int*)d_in[1];
    float* out = (float*)d_out;

    cudaFuncSetAttribute(gemm_kernel, cudaFuncAttributeMaxDynamicSharedMemorySize, SMEM_GEMM);

    prep_emb<<<(NB * ND / 8) / 256, 256>>>(emb);
    prep_misc<<<NB / 256, 256>>>(labels);
    prep_cls<<<1, 1024>>>(labels);
    gemm_kernel<<<dim3(64, 64), 256, SMEM_GEMM>>>(labels);
    row_kernel<<<NB, 256>>>();
    final_kernel<<<1, 1024>>>(out);
}